// round 13
// baseline (speedup 1.0000x reference)
#include <cuda_runtime.h>
#include <cuda_bf16.h>
#include <cstdint>

// ---------------------------------------------------------------------------
// MHA cross-attention, all GEMMs on mma.sync bf16x3-split (fp32-grade).
//   proj q/k/v: fp32 in -> bf16 hi/lo out (scatter [b][h][t][d], scale folded
//               into Q);  flash attention: HMMA S=QK^T and O=PV with online
//               softmax in registers;  out-proj: fp32 path unchanged.
// ---------------------------------------------------------------------------

constexpr int T_  = 2048;
constexpr int B_  = 4;
constexpr int C_  = 1024;
constexpr int H_  = 16;
constexpr int HD_ = 64;
constexpr int M_  = T_ * B_;   // 8192 rows

// Scratch (device globals: allocation-free per harness rules).
__device__ __nv_bfloat16 g_Qh[M_ * C_];
__device__ __nv_bfloat16 g_Ql[M_ * C_];
__device__ __nv_bfloat16 g_Kh[M_ * C_];
__device__ __nv_bfloat16 g_Kl[M_ * C_];
__device__ __nv_bfloat16 g_Vh[M_ * C_];
__device__ __nv_bfloat16 g_Vl[M_ * C_];
__device__ float         g_AO[M_ * C_];

// ============================ helpers ======================================
__device__ __forceinline__ uint32_t smem_u32(const void* p) {
    uint32_t a;
    asm("{ .reg .u64 t; cvta.to.shared.u64 t, %1; cvt.u32.u64 %0, t; }"
        : "=r"(a) : "l"(p));
    return a;
}
__device__ __forceinline__ void ldsm4(uint32_t& r0, uint32_t& r1,
                                      uint32_t& r2, uint32_t& r3, uint32_t a) {
    asm volatile("ldmatrix.sync.aligned.m8n8.x4.shared.b16 {%0,%1,%2,%3}, [%4];"
                 : "=r"(r0), "=r"(r1), "=r"(r2), "=r"(r3) : "r"(a));
}
__device__ __forceinline__ void ldsm4t(uint32_t& r0, uint32_t& r1,
                                       uint32_t& r2, uint32_t& r3, uint32_t a) {
    asm volatile("ldmatrix.sync.aligned.m8n8.x4.trans.shared.b16 {%0,%1,%2,%3}, [%4];"
                 : "=r"(r0), "=r"(r1), "=r"(r2), "=r"(r3) : "r"(a));
}
__device__ __forceinline__ void mma_bf16(float* c, const uint32_t* a,
                                         const uint32_t* b) {
    asm volatile(
        "mma.sync.aligned.m16n8k16.row.col.f32.bf16.bf16.f32 "
        "{%0,%1,%2,%3}, {%4,%5,%6,%7}, {%8,%9}, {%0,%1,%2,%3};"
        : "+f"(c[0]), "+f"(c[1]), "+f"(c[2]), "+f"(c[3])
        : "r"(a[0]), "r"(a[1]), "r"(a[2]), "r"(a[3]), "r"(b[0]), "r"(b[1]));
}
// pack two fp32 into bf16x2 (lo -> low half)
__device__ __forceinline__ uint32_t pack_bf16(float lo, float hi) {
    uint32_t r;
    asm("cvt.rn.bf16x2.f32 %0, %1, %2;" : "=r"(r) : "f"(hi), "f"(lo));
    return r;
}
// split two fp32 into (hi-word, lo-word) bf16x2 pairs
__device__ __forceinline__ void split2(float a, float b, uint32_t& hw, uint32_t& lw) {
    float ha = __bfloat162float(__float2bfloat16_rn(a));
    float hb = __bfloat162float(__float2bfloat16_rn(b));
    hw = pack_bf16(a, b);                  // rn again: identical rounding
    lw = pack_bf16(a - ha, b - hb);
}
// fp32x4 -> (hi bf16x4, lo bf16x4) packed as uint2 each
__device__ __forceinline__ void split4(float4 v, uint2& h, uint2& l) {
    split2(v.x, v.y, h.x, l.x);
    split2(v.z, v.w, h.y, l.y);
}

// ============================ projection ===================================
// Y = X(MxK) @ W^T(NxK) + bias,  bf16x3 split on mma.sync.
// Block tile 128x128, K-chunk 32 fp32. 8 warps, warp tile 64x32.
constexpr int PROJ_BUF  = 4 * 128 * 32 * 2;   // 32768 B
constexpr int PROJ_SMEM = 2 * PROJ_BUF;       // 65536 B (double buffered)

// MODE 0: write bf16 hi/lo scattered to [b][h][t][d] (scale folded).
// MODE 1: write fp32 Y[r*C+n].
template <int MODE>
__global__ void __launch_bounds__(256, 1) proj_mma(
    const float* __restrict__ X, const float* __restrict__ W,
    const float* __restrict__ bias, float* __restrict__ Yf,
    __nv_bfloat16* __restrict__ Yh, __nv_bfloat16* __restrict__ Yl,
    float scale)
{
    extern __shared__ char smem[];
    const uint32_t sbase = smem_u32(smem);
    const int tid = threadIdx.x;
    const int wid = tid >> 5;
    const int lid = tid & 31;
    const int bm  = blockIdx.y * 128;
    const int bn  = blockIdx.x * 128;

    const int wm = wid & 1;        // 2 m-tiles of 64
    const int wn = wid >> 1;       // 4 n-tiles of 32

    const int rA = lid & 15;
    const int cA = lid >> 4;
    const int rB = ((lid >> 4) << 3) + (lid & 7);
    const int cB = (lid >> 3) & 1;

    int grow[4], gc4[4];
#pragma unroll
    for (int i = 0; i < 4; i++) {
        const int f = tid + i * 256;
        grow[i] = f >> 3;
        gc4[i]  = f & 7;
    }

    float acc[4][4][4];
#pragma unroll
    for (int mf = 0; mf < 4; mf++)
#pragma unroll
        for (int nf = 0; nf < 4; nf++)
#pragma unroll
            for (int j = 0; j < 4; j++) acc[mf][nf][j] = 0.f;

    float4 ga[4], gb[4];

    auto load_regs = [&](int kt) {
#pragma unroll
        for (int i = 0; i < 4; i++) {
            ga[i] = *(const float4*)(X + (size_t)(bm + grow[i]) * C_ + kt * 32 + gc4[i] * 4);
            gb[i] = *(const float4*)(W + (size_t)(bn + grow[i]) * C_ + kt * 32 + gc4[i] * 4);
        }
    };
    auto store_split = [&](char* buf) {
#pragma unroll
        for (int i = 0; i < 4; i++) {
            const int row = grow[i], c4 = gc4[i];
            const uint32_t o = row * 64 +
                ((((c4 >> 1) ^ ((row >> 1) & 3))) << 4) + (c4 & 1) * 8;
            uint2 h, l;
            split4(ga[i], h, l);
            *(uint2*)(buf + o)         = h;
            *(uint2*)(buf + 8192 + o)  = l;
            split4(gb[i], h, l);
            *(uint2*)(buf + 16384 + o) = h;
            *(uint2*)(buf + 24576 + o) = l;
        }
    };
    auto compute = [&](uint32_t bb) {
        const uint32_t ahi = bb, alo = bb + 8192, bhi = bb + 16384, blo = bb + 24576;
#pragma unroll
        for (int ks = 0; ks < 2; ks++) {
            uint32_t bh[4][2], bl[4][2];
#pragma unroll
            for (int p = 0; p < 2; p++) {
                const int rowB = wn * 32 + p * 16 + rB;
                const uint32_t off = rowB * 64 +
                    (((ks * 2 + cB) ^ ((rowB >> 1) & 3)) << 4);
                ldsm4(bh[2*p][0], bh[2*p][1], bh[2*p+1][0], bh[2*p+1][1], bhi + off);
                ldsm4(bl[2*p][0], bl[2*p][1], bl[2*p+1][0], bl[2*p+1][1], blo + off);
            }
#pragma unroll
            for (int mf = 0; mf < 4; mf++) {
                const int rowA = wm * 64 + mf * 16 + rA;
                const uint32_t off = rowA * 64 +
                    (((ks * 2 + cA) ^ ((rowA >> 1) & 3)) << 4);
                uint32_t ah[4], al[4];
                ldsm4(ah[0], ah[1], ah[2], ah[3], ahi + off);
                ldsm4(al[0], al[1], al[2], al[3], alo + off);
#pragma unroll
                for (int nf = 0; nf < 4; nf++) {
                    mma_bf16(acc[mf][nf], ah, bh[nf]);
                    mma_bf16(acc[mf][nf], ah, bl[nf]);
                    mma_bf16(acc[mf][nf], al, bh[nf]);
                }
            }
        }
    };

    load_regs(0);
    store_split(smem);
    __syncthreads();
    int cur = 0;
    const int NCHUNK = C_ / 32;
    for (int kt = 0; kt < NCHUNK; kt++) {
        const bool has_next = (kt + 1) < NCHUNK;
        if (has_next) load_regs(kt + 1);
        compute(sbase + cur * PROJ_BUF);
        if (has_next) {
            store_split(smem + (cur ^ 1) * PROJ_BUF);
            __syncthreads();
            cur ^= 1;
        }
    }

#pragma unroll
    for (int mf = 0; mf < 4; mf++) {
        const int m = bm + wm * 64 + mf * 16 + (lid >> 2);
#pragma unroll
        for (int nf = 0; nf < 4; nf++) {
            const int n0 = bn + wn * 32 + nf * 8 + (lid & 3) * 2;
            const float2 bb = *(const float2*)(bias + n0);
            float v00 = acc[mf][nf][0] + bb.x, v01 = acc[mf][nf][1] + bb.y;
            float v10 = acc[mf][nf][2] + bb.x, v11 = acc[mf][nf][3] + bb.y;
            if (MODE == 0) {
                v00 *= scale; v01 *= scale; v10 *= scale; v11 *= scale;
                const int h = n0 >> 6, d = n0 & 63;
                uint32_t hw, lw;
                int t = m >> 2, b2 = m & 3;
                size_t idx = ((size_t)(b2 * H_ + h) * T_ + t) * HD_ + d;
                split2(v00, v01, hw, lw);
                *(uint32_t*)(Yh + idx) = hw;
                *(uint32_t*)(Yl + idx) = lw;
                t = (m + 8) >> 2; b2 = (m + 8) & 3;
                idx = ((size_t)(b2 * H_ + h) * T_ + t) * HD_ + d;
                split2(v10, v11, hw, lw);
                *(uint32_t*)(Yh + idx) = hw;
                *(uint32_t*)(Yl + idx) = lw;
            } else {
                *(float2*)&Yf[(size_t)m * C_ + n0]       = make_float2(v00, v01);
                *(float2*)&Yf[(size_t)(m + 8) * C_ + n0] = make_float2(v10, v11);
            }
        }
    }
}

// ============================ flash attention (HMMA) =======================
// CTA: 128 queries of one (b,h). 8 warps x 16 queries. K-tiles of 128 keys.
// smem: Qh Ql Kh Kl Vh Vl, each [128][64] bf16 = 16KB (128B rows, XOR swizzle
// off = r*128 + ((chunk ^ (r&7))<<4)).  Total 96KB.
constexpr int ATT_SMEM = 6 * 16384;

__global__ void __launch_bounds__(256, 1) attn_mma(
    const __nv_bfloat16* __restrict__ Qh, const __nv_bfloat16* __restrict__ Ql,
    const __nv_bfloat16* __restrict__ Kh, const __nv_bfloat16* __restrict__ Kl,
    const __nv_bfloat16* __restrict__ Vh, const __nv_bfloat16* __restrict__ Vl,
    float* __restrict__ AO)
{
    extern __shared__ char sm[];
    const uint32_t aQh = smem_u32(sm);
    const uint32_t aQl = aQh + 16384;
    const uint32_t aKh = aQh + 32768;
    const uint32_t aKl = aQh + 49152;
    const uint32_t aVh = aQh + 65536;
    const uint32_t aVl = aQh + 81920;

    const int tid = threadIdx.x, wid = tid >> 5, lid = tid & 31;
    const int g = lid >> 2, t = lid & 3;
    const int b = blockIdx.z, h = blockIdx.y, q0 = blockIdx.x * 128;
    const size_t base = (size_t)(b * H_ + h) * T_ * HD_;

    // ---- load Q tile (once) ----
    for (int i = tid; i < 1024; i += 256) {
        const int r = i >> 3, c = i & 7;
        const uint32_t off = r * 128 + ((c ^ (r & 7)) << 4);
        const size_t go = base + (size_t)(q0 + r) * HD_;
        *(uint4*)(sm + off)         = *(const uint4*)((const char*)(Qh + go) + c * 16);
        *(uint4*)(sm + 16384 + off) = *(const uint4*)((const char*)(Ql + go) + c * 16);
    }
    __syncthreads();

    // Q fragments in registers for the whole kernel
    uint32_t qh[4][4], ql[4][4];
    {
        const int rowA = wid * 16 + (lid & 15);
#pragma unroll
        for (int ks = 0; ks < 4; ks++) {
            const int ch = ks * 2 + (lid >> 4);
            const uint32_t off = rowA * 128 + ((ch ^ (rowA & 7)) << 4);
            ldsm4(qh[ks][0], qh[ks][1], qh[ks][2], qh[ks][3], aQh + off);
            ldsm4(ql[ks][0], ql[ks][1], ql[ks][2], ql[ks][3], aQl + off);
        }
    }

    float oacc[8][4];
#pragma unroll
    for (int nf = 0; nf < 8; nf++)
#pragma unroll
        for (int j = 0; j < 4; j++) oacc[nf][j] = 0.f;
    float m0 = -1e30f, m1 = -1e30f, l0 = 0.f, l1 = 0.f;

    for (int kt = 0; kt < 16; kt++) {
        const int k0 = kt * 128;
        __syncthreads();   // previous tile's K/V reads done
        for (int i = tid; i < 1024; i += 256) {
            const int r = i >> 3, c = i & 7;
            const uint32_t off = r * 128 + ((c ^ (r & 7)) << 4);
            const size_t go = base + (size_t)(k0 + r) * HD_;
            *(uint4*)(sm + 32768 + off) = *(const uint4*)((const char*)(Kh + go) + c * 16);
            *(uint4*)(sm + 49152 + off) = *(const uint4*)((const char*)(Kl + go) + c * 16);
            *(uint4*)(sm + 65536 + off) = *(const uint4*)((const char*)(Vh + go) + c * 16);
            *(uint4*)(sm + 81920 + off) = *(const uint4*)((const char*)(Vl + go) + c * 16);
        }
        __syncthreads();

        // ---- S = Q K^T (x3 split) ----
        float sacc[16][4];
#pragma unroll
        for (int nf = 0; nf < 16; nf++)
#pragma unroll
            for (int j = 0; j < 4; j++) sacc[nf][j] = 0.f;

#pragma unroll
        for (int ks = 0; ks < 4; ks++) {
#pragma unroll
            for (int p = 0; p < 8; p++) {
                const int rowB = p * 16 + ((lid >> 4) << 3) + (lid & 7);
                const int ch = ks * 2 + ((lid >> 3) & 1);
                const uint32_t off = rowB * 128 + ((ch ^ (rowB & 7)) << 4);
                uint32_t bh[4], bl[4];
                ldsm4(bh[0], bh[1], bh[2], bh[3], aKh + off);
                ldsm4(bl[0], bl[1], bl[2], bl[3], aKl + off);
                mma_bf16(sacc[2*p],   qh[ks], bh);
                mma_bf16(sacc[2*p],   ql[ks], bh);
                mma_bf16(sacc[2*p],   qh[ks], bl);
                mma_bf16(sacc[2*p+1], qh[ks], bh + 2);
                mma_bf16(sacc[2*p+1], ql[ks], bh + 2);
                mma_bf16(sacc[2*p+1], qh[ks], bl + 2);
            }
        }

        // ---- online softmax (rows g and g+8, warp-local) ----
        float rmax0 = -1e30f, rmax1 = -1e30f;
#pragma unroll
        for (int nf = 0; nf < 16; nf++) {
            rmax0 = fmaxf(rmax0, fmaxf(sacc[nf][0], sacc[nf][1]));
            rmax1 = fmaxf(rmax1, fmaxf(sacc[nf][2], sacc[nf][3]));
        }
        rmax0 = fmaxf(rmax0, __shfl_xor_sync(0xffffffffu, rmax0, 1));
        rmax0 = fmaxf(rmax0, __shfl_xor_sync(0xffffffffu, rmax0, 2));
        rmax1 = fmaxf(rmax1, __shfl_xor_sync(0xffffffffu, rmax1, 1));
        rmax1 = fmaxf(rmax1, __shfl_xor_sync(0xffffffffu, rmax1, 2));
        const float mn0 = fmaxf(m0, rmax0), mn1 = fmaxf(m1, rmax1);
        const float c0 = __expf(m0 - mn0), c1 = __expf(m1 - mn1);
        m0 = mn0; m1 = mn1;
        float rs0 = 0.f, rs1 = 0.f;
#pragma unroll
        for (int nf = 0; nf < 16; nf++) {
            sacc[nf][0] = __expf(sacc[nf][0] - m0);
            sacc[nf][1] = __expf(sacc[nf][1] - m0);
            sacc[nf][2] = __expf(sacc[nf][2] - m1);
            sacc[nf][3] = __expf(sacc[nf][3] - m1);
            rs0 += sacc[nf][0] + sacc[nf][1];
            rs1 += sacc[nf][2] + sacc[nf][3];
        }
        rs0 += __shfl_xor_sync(0xffffffffu, rs0, 1);
        rs0 += __shfl_xor_sync(0xffffffffu, rs0, 2);
        rs1 += __shfl_xor_sync(0xffffffffu, rs1, 1);
        rs1 += __shfl_xor_sync(0xffffffffu, rs1, 2);
        l0 = l0 * c0 + rs0;
        l1 = l1 * c1 + rs1;
#pragma unroll
        for (int nf = 0; nf < 8; nf++) {
            oacc[nf][0] *= c0; oacc[nf][1] *= c0;
            oacc[nf][2] *= c1; oacc[nf][3] *= c1;
        }

        // ---- O += P V (x3 split); P frags packed from sacc ----
#pragma unroll
        for (int ks = 0; ks < 8; ks++) {
            uint32_t ph[4], pl[4];
            split2(sacc[2*ks][0],   sacc[2*ks][1],   ph[0], pl[0]);
            split2(sacc[2*ks][2],   sacc[2*ks][3],   ph[1], pl[1]);
            split2(sacc[2*ks+1][0], sacc[2*ks+1][1], ph[2], pl[2]);
            split2(sacc[2*ks+1][2], sacc[2*ks+1][3], ph[3], pl[3]);
            const int rowV = ks * 16 + ((lid >> 3) & 1) * 8 + (lid & 7);
#pragma unroll
            for (int dv = 0; dv < 4; dv++) {
                const int ch = dv * 2 + (lid >> 4);
                const uint32_t off = rowV * 128 + ((ch ^ (rowV & 7)) << 4);
                uint32_t vh[4], vl[4];
                ldsm4t(vh[0], vh[1], vh[2], vh[3], aVh + off);
                ldsm4t(vl[0], vl[1], vl[2], vl[3], aVl + off);
                mma_bf16(oacc[2*dv],   ph, vh);
                mma_bf16(oacc[2*dv],   pl, vh);
                mma_bf16(oacc[2*dv],   ph, vl);
                mma_bf16(oacc[2*dv+1], ph, vh + 2);
                mma_bf16(oacc[2*dv+1], pl, vh + 2);
                mma_bf16(oacc[2*dv+1], ph, vl + 2);
            }
        }
    }

    // ---- epilogue: AO[b][q][h*64+d] = O / l ----
    const float inv0 = 1.f / l0, inv1 = 1.f / l1;
    const int qa = q0 + wid * 16 + g;
#pragma unroll
    for (int nf = 0; nf < 8; nf++) {
        const int d = h * 64 + nf * 8 + t * 2;
        *(float2*)&AO[(size_t)(b * T_ + qa) * C_ + d] =
            make_float2(oacc[nf][0] * inv0, oacc[nf][1] * inv0);
        *(float2*)&AO[(size_t)(b * T_ + qa + 8) * C_ + d] =
            make_float2(oacc[nf][2] * inv1, oacc[nf][3] * inv1);
    }
}

// ---------------------------------------------------------------------------
extern "C" void kernel_launch(void* const* d_in, const int* in_sizes, int n_in,
                              void* d_out, int out_size)
{
    (void)in_sizes; (void)n_in; (void)out_size;
    const float* x1 = (const float*)d_in[0];
    const float* x2 = (const float*)d_in[1];
    const float* Wq = (const float*)d_in[2];
    const float* bq = (const float*)d_in[3];
    const float* Wk = (const float*)d_in[4];
    const float* bk = (const float*)d_in[5];
    const float* Wv = (const float*)d_in[6];
    const float* bv = (const float*)d_in[7];
    const float* Wu = (const float*)d_in[8];
    const float* bu = (const float*)d_in[9];
    float* out = (float*)d_out;

    __nv_bfloat16 *qh, *ql, *kh, *kl, *vh, *vl;
    float* aop;
    cudaGetSymbolAddress((void**)&qh, g_Qh);
    cudaGetSymbolAddress((void**)&ql, g_Ql);
    cudaGetSymbolAddress((void**)&kh, g_Kh);
    cudaGetSymbolAddress((void**)&kl, g_Kl);
    cudaGetSymbolAddress((void**)&vh, g_Vh);
    cudaGetSymbolAddress((void**)&vl, g_Vl);
    cudaGetSymbolAddress((void**)&aop, g_AO);

    cudaFuncSetAttribute(proj_mma<0>, cudaFuncAttributeMaxDynamicSharedMemorySize, PROJ_SMEM);
    cudaFuncSetAttribute(proj_mma<1>, cudaFuncAttributeMaxDynamicSharedMemorySize, PROJ_SMEM);
    cudaFuncSetAttribute(attn_mma,    cudaFuncAttributeMaxDynamicSharedMemorySize, ATT_SMEM);

    const float SCALE = 0.03125f;   // 1/sqrt(1024)
    dim3 gp(C_ / 128, M_ / 128);    // (8, 64)
    proj_mma<0><<<gp, 256, PROJ_SMEM>>>(x1, Wq, bq, nullptr, qh, ql, SCALE);
    proj_mma<0><<<gp, 256, PROJ_SMEM>>>(x2, Wk, bk, nullptr, kh, kl, 1.f);
    proj_mma<0><<<gp, 256, PROJ_SMEM>>>(x2, Wv, bv, nullptr, vh, vl, 1.f);
    attn_mma<<<dim3(T_ / 128, H_, B_), 256, ATT_SMEM>>>(qh, ql, kh, kl, vh, vl, aop);
    proj_mma<1><<<gp, 256, PROJ_SMEM>>>(aop, Wu, bu, out, nullptr, nullptr, 1.f);
}

// round 14
// speedup vs baseline: 1.2780x; 1.2780x over previous
#include <cuda_runtime.h>
#include <cuda_bf16.h>
#include <cuda_fp16.h>
#include <cstdint>

// ---------------------------------------------------------------------------
// MHA cross-attention.
//   proj q/k/v: bf16x3-split HMMA GEMM (fp32-grade), fp32 in -> fp16 out
//               scattered [b][h][t][d]; Q scale folds 1/sqrt(C) * log2(e).
//   attention:  fp16 single-term HMMA flash kernel, softmax in log2 domain.
//   out-proj:   bf16x3-split HMMA, fp32 out.
// ---------------------------------------------------------------------------

constexpr int T_  = 2048;
constexpr int B_  = 4;
constexpr int C_  = 1024;
constexpr int H_  = 16;
constexpr int HD_ = 64;
constexpr int M_  = T_ * B_;   // 8192 rows

// Scratch (device globals: allocation-free per harness rules).
__device__ __half g_Qf[M_ * C_];
__device__ __half g_Kf[M_ * C_];
__device__ __half g_Vf[M_ * C_];
__device__ float  g_AO[M_ * C_];

// ============================ helpers ======================================
__device__ __forceinline__ uint32_t smem_u32(const void* p) {
    uint32_t a;
    asm("{ .reg .u64 t; cvta.to.shared.u64 t, %1; cvt.u32.u64 %0, t; }"
        : "=r"(a) : "l"(p));
    return a;
}
__device__ __forceinline__ void ldsm4(uint32_t& r0, uint32_t& r1,
                                      uint32_t& r2, uint32_t& r3, uint32_t a) {
    asm volatile("ldmatrix.sync.aligned.m8n8.x4.shared.b16 {%0,%1,%2,%3}, [%4];"
                 : "=r"(r0), "=r"(r1), "=r"(r2), "=r"(r3) : "r"(a));
}
__device__ __forceinline__ void ldsm4t(uint32_t& r0, uint32_t& r1,
                                       uint32_t& r2, uint32_t& r3, uint32_t a) {
    asm volatile("ldmatrix.sync.aligned.m8n8.x4.trans.shared.b16 {%0,%1,%2,%3}, [%4];"
                 : "=r"(r0), "=r"(r1), "=r"(r2), "=r"(r3) : "r"(a));
}
__device__ __forceinline__ void mma_bf16(float* c, const uint32_t* a,
                                         const uint32_t* b) {
    asm volatile(
        "mma.sync.aligned.m16n8k16.row.col.f32.bf16.bf16.f32 "
        "{%0,%1,%2,%3}, {%4,%5,%6,%7}, {%8,%9}, {%0,%1,%2,%3};"
        : "+f"(c[0]), "+f"(c[1]), "+f"(c[2]), "+f"(c[3])
        : "r"(a[0]), "r"(a[1]), "r"(a[2]), "r"(a[3]), "r"(b[0]), "r"(b[1]));
}
__device__ __forceinline__ void mma_f16(float* c, const uint32_t* a,
                                        const uint32_t* b) {
    asm volatile(
        "mma.sync.aligned.m16n8k16.row.col.f32.f16.f16.f32 "
        "{%0,%1,%2,%3}, {%4,%5,%6,%7}, {%8,%9}, {%0,%1,%2,%3};"
        : "+f"(c[0]), "+f"(c[1]), "+f"(c[2]), "+f"(c[3])
        : "r"(a[0]), "r"(a[1]), "r"(a[2]), "r"(a[3]), "r"(b[0]), "r"(b[1]));
}
// pack two fp32 into bf16x2 / f16x2 (first arg -> low half)
__device__ __forceinline__ uint32_t pack_bf16(float lo, float hi) {
    uint32_t r;
    asm("cvt.rn.bf16x2.f32 %0, %1, %2;" : "=r"(r) : "f"(hi), "f"(lo));
    return r;
}
__device__ __forceinline__ uint32_t pack_h16(float lo, float hi) {
    uint32_t r;
    asm("cvt.rn.f16x2.f32 %0, %1, %2;" : "=r"(r) : "f"(hi), "f"(lo));
    return r;
}
__device__ __forceinline__ float ex2f(float x) {
    float y;
    asm("ex2.approx.f32 %0, %1;" : "=f"(y) : "f"(x));
    return y;
}
// split two fp32 into (hi-word, lo-word) bf16x2 pairs
__device__ __forceinline__ void split2(float a, float b, uint32_t& hw, uint32_t& lw) {
    float ha = __bfloat162float(__float2bfloat16_rn(a));
    float hb = __bfloat162float(__float2bfloat16_rn(b));
    hw = pack_bf16(a, b);
    lw = pack_bf16(a - ha, b - hb);
}
__device__ __forceinline__ void split4(float4 v, uint2& h, uint2& l) {
    split2(v.x, v.y, h.x, l.x);
    split2(v.z, v.w, h.y, l.y);
}

// ============================ projection ===================================
// Y = X(MxK) @ W^T(NxK) + bias,  bf16x3 split on mma.sync.
// Block tile 128x128, K-chunk 32 fp32. 8 warps, warp tile 64x32.
constexpr int PROJ_BUF  = 4 * 128 * 32 * 2;   // 32768 B
constexpr int PROJ_SMEM = 2 * PROJ_BUF;       // 65536 B (double buffered)

// MODE 0: write fp16 scattered to [b][h][t][d] (scale folded).
// MODE 1: write fp32 Y[r*C+n].
template <int MODE>
__global__ void __launch_bounds__(256, 1) proj_mma(
    const float* __restrict__ X, const float* __restrict__ W,
    const float* __restrict__ bias, float* __restrict__ Yf,
    __half* __restrict__ Yh, float scale)
{
    extern __shared__ char smem[];
    const uint32_t sbase = smem_u32(smem);
    const int tid = threadIdx.x;
    const int wid = tid >> 5;
    const int lid = tid & 31;
    const int bm  = blockIdx.y * 128;
    const int bn  = blockIdx.x * 128;

    const int wm = wid & 1;
    const int wn = wid >> 1;

    const int rA = lid & 15;
    const int cA = lid >> 4;
    const int rB = ((lid >> 4) << 3) + (lid & 7);
    const int cB = (lid >> 3) & 1;

    int grow[4], gc4[4];
#pragma unroll
    for (int i = 0; i < 4; i++) {
        const int f = tid + i * 256;
        grow[i] = f >> 3;
        gc4[i]  = f & 7;
    }

    float acc[4][4][4];
#pragma unroll
    for (int mf = 0; mf < 4; mf++)
#pragma unroll
        for (int nf = 0; nf < 4; nf++)
#pragma unroll
            for (int j = 0; j < 4; j++) acc[mf][nf][j] = 0.f;

    float4 ga[4], gb[4];

    auto load_regs = [&](int kt) {
#pragma unroll
        for (int i = 0; i < 4; i++) {
            ga[i] = *(const float4*)(X + (size_t)(bm + grow[i]) * C_ + kt * 32 + gc4[i] * 4);
            gb[i] = *(const float4*)(W + (size_t)(bn + grow[i]) * C_ + kt * 32 + gc4[i] * 4);
        }
    };
    auto store_split = [&](char* buf) {
#pragma unroll
        for (int i = 0; i < 4; i++) {
            const int row = grow[i], c4 = gc4[i];
            const uint32_t o = row * 64 +
                ((((c4 >> 1) ^ ((row >> 1) & 3))) << 4) + (c4 & 1) * 8;
            uint2 h, l;
            split4(ga[i], h, l);
            *(uint2*)(buf + o)         = h;
            *(uint2*)(buf + 8192 + o)  = l;
            split4(gb[i], h, l);
            *(uint2*)(buf + 16384 + o) = h;
            *(uint2*)(buf + 24576 + o) = l;
        }
    };
    auto compute = [&](uint32_t bb) {
        const uint32_t ahi = bb, alo = bb + 8192, bhi = bb + 16384, blo = bb + 24576;
#pragma unroll
        for (int ks = 0; ks < 2; ks++) {
            uint32_t bh[4][2], bl[4][2];
#pragma unroll
            for (int p = 0; p < 2; p++) {
                const int rowB = wn * 32 + p * 16 + rB;
                const uint32_t off = rowB * 64 +
                    (((ks * 2 + cB) ^ ((rowB >> 1) & 3)) << 4);
                ldsm4(bh[2*p][0], bh[2*p][1], bh[2*p+1][0], bh[2*p+1][1], bhi + off);
                ldsm4(bl[2*p][0], bl[2*p][1], bl[2*p+1][0], bl[2*p+1][1], blo + off);
            }
#pragma unroll
            for (int mf = 0; mf < 4; mf++) {
                const int rowA = wm * 64 + mf * 16 + rA;
                const uint32_t off = rowA * 64 +
                    (((ks * 2 + cA) ^ ((rowA >> 1) & 3)) << 4);
                uint32_t ah[4], al[4];
                ldsm4(ah[0], ah[1], ah[2], ah[3], ahi + off);
                ldsm4(al[0], al[1], al[2], al[3], alo + off);
#pragma unroll
                for (int nf = 0; nf < 4; nf++) {
                    mma_bf16(acc[mf][nf], ah, bh[nf]);
                    mma_bf16(acc[mf][nf], ah, bl[nf]);
                    mma_bf16(acc[mf][nf], al, bh[nf]);
                }
            }
        }
    };

    load_regs(0);
    store_split(smem);
    __syncthreads();
    int cur = 0;
    const int NCHUNK = C_ / 32;
    for (int kt = 0; kt < NCHUNK; kt++) {
        const bool has_next = (kt + 1) < NCHUNK;
        if (has_next) load_regs(kt + 1);
        compute(sbase + cur * PROJ_BUF);
        if (has_next) {
            store_split(smem + (cur ^ 1) * PROJ_BUF);
            __syncthreads();
            cur ^= 1;
        }
    }

#pragma unroll
    for (int mf = 0; mf < 4; mf++) {
        const int m = bm + wm * 64 + mf * 16 + (lid >> 2);
#pragma unroll
        for (int nf = 0; nf < 4; nf++) {
            const int n0 = bn + wn * 32 + nf * 8 + (lid & 3) * 2;
            const float2 bb = *(const float2*)(bias + n0);
            float v00 = acc[mf][nf][0] + bb.x, v01 = acc[mf][nf][1] + bb.y;
            float v10 = acc[mf][nf][2] + bb.x, v11 = acc[mf][nf][3] + bb.y;
            if (MODE == 0) {
                v00 *= scale; v01 *= scale; v10 *= scale; v11 *= scale;
                const int h = n0 >> 6, d = n0 & 63;
                int t = m >> 2, b2 = m & 3;
                size_t idx = ((size_t)(b2 * H_ + h) * T_ + t) * HD_ + d;
                *(uint32_t*)(Yh + idx) = pack_h16(v00, v01);
                t = (m + 8) >> 2; b2 = (m + 8) & 3;
                idx = ((size_t)(b2 * H_ + h) * T_ + t) * HD_ + d;
                *(uint32_t*)(Yh + idx) = pack_h16(v10, v11);
            } else {
                *(float2*)&Yf[(size_t)m * C_ + n0]       = make_float2(v00, v01);
                *(float2*)&Yf[(size_t)(m + 8) * C_ + n0] = make_float2(v10, v11);
            }
        }
    }
}

// ============================ flash attention (fp16 HMMA) ==================
// CTA: 128 queries of one (b,h). 8 warps x 16 queries. K-tiles of 128 keys.
// smem: Q K V, each [128][64] fp16 = 16KB (128B rows, XOR swizzle
// off = r*128 + ((chunk ^ (r&7))<<4)).  Total 48KB.
// Q pre-scaled by (1/sqrt(C))*log2(e): softmax runs in log2 domain (ex2).
constexpr int ATT_SMEM = 3 * 16384;

__global__ void __launch_bounds__(256, 1) attn_mma(
    const __half* __restrict__ Qf, const __half* __restrict__ Kf,
    const __half* __restrict__ Vf, float* __restrict__ AO)
{
    extern __shared__ char sm[];
    const uint32_t aQ = smem_u32(sm);
    const uint32_t aK = aQ + 16384;
    const uint32_t aV = aQ + 32768;

    const int tid = threadIdx.x, wid = tid >> 5, lid = tid & 31;
    const int g = lid >> 2, t = lid & 3;
    const int b = blockIdx.z, h = blockIdx.y, q0 = blockIdx.x * 128;
    const size_t base = (size_t)(b * H_ + h) * T_ * HD_;

    // ---- load Q tile (once) ----
    for (int i = tid; i < 1024; i += 256) {
        const int r = i >> 3, c = i & 7;
        const uint32_t off = r * 128 + ((c ^ (r & 7)) << 4);
        *(uint4*)(sm + off) =
            *(const uint4*)((const char*)(Qf + base + (size_t)(q0 + r) * HD_) + c * 16);
    }
    __syncthreads();

    // Q fragments in registers for the whole kernel
    uint32_t qf[4][4];
    {
        const int rowA = wid * 16 + (lid & 15);
#pragma unroll
        for (int ks = 0; ks < 4; ks++) {
            const int ch = ks * 2 + (lid >> 4);
            const uint32_t off = rowA * 128 + ((ch ^ (rowA & 7)) << 4);
            ldsm4(qf[ks][0], qf[ks][1], qf[ks][2], qf[ks][3], aQ + off);
        }
    }

    float oacc[8][4];
#pragma unroll
    for (int nf = 0; nf < 8; nf++)
#pragma unroll
        for (int j = 0; j < 4; j++) oacc[nf][j] = 0.f;
    float m0 = -1e30f, m1 = -1e30f, l0 = 0.f, l1 = 0.f;

    for (int kt = 0; kt < 16; kt++) {
        const int k0 = kt * 128;
        __syncthreads();   // previous tile's K/V reads done
        for (int i = tid; i < 1024; i += 256) {
            const int r = i >> 3, c = i & 7;
            const uint32_t off = r * 128 + ((c ^ (r & 7)) << 4);
            const size_t go = base + (size_t)(k0 + r) * HD_;
            *(uint4*)(sm + 16384 + off) = *(const uint4*)((const char*)(Kf + go) + c * 16);
            *(uint4*)(sm + 32768 + off) = *(const uint4*)((const char*)(Vf + go) + c * 16);
        }
        __syncthreads();

        // ---- S = Q K^T (single fp16 term; S already in log2 units) ----
        float sacc[16][4];
#pragma unroll
        for (int nf = 0; nf < 16; nf++)
#pragma unroll
            for (int j = 0; j < 4; j++) sacc[nf][j] = 0.f;

#pragma unroll
        for (int ks = 0; ks < 4; ks++) {
#pragma unroll
            for (int p = 0; p < 8; p++) {
                const int rowB = p * 16 + ((lid >> 4) << 3) + (lid & 7);
                const int ch = ks * 2 + ((lid >> 3) & 1);
                const uint32_t off = rowB * 128 + ((ch ^ (rowB & 7)) << 4);
                uint32_t kfrag[4];
                ldsm4(kfrag[0], kfrag[1], kfrag[2], kfrag[3], aK + off);
                mma_f16(sacc[2*p],   qf[ks], kfrag);
                mma_f16(sacc[2*p+1], qf[ks], kfrag + 2);
            }
        }

        // ---- online softmax in log2 domain (rows g, g+8; warp-local) ----
        float rmax0 = -1e30f, rmax1 = -1e30f;
#pragma unroll
        for (int nf = 0; nf < 16; nf++) {
            rmax0 = fmaxf(rmax0, fmaxf(sacc[nf][0], sacc[nf][1]));
            rmax1 = fmaxf(rmax1, fmaxf(sacc[nf][2], sacc[nf][3]));
        }
        rmax0 = fmaxf(rmax0, __shfl_xor_sync(0xffffffffu, rmax0, 1));
        rmax0 = fmaxf(rmax0, __shfl_xor_sync(0xffffffffu, rmax0, 2));
        rmax1 = fmaxf(rmax1, __shfl_xor_sync(0xffffffffu, rmax1, 1));
        rmax1 = fmaxf(rmax1, __shfl_xor_sync(0xffffffffu, rmax1, 2));
        const float mn0 = fmaxf(m0, rmax0), mn1 = fmaxf(m1, rmax1);
        const float c0 = ex2f(m0 - mn0), c1 = ex2f(m1 - mn1);
        m0 = mn0; m1 = mn1;
        float rs0 = 0.f, rs1 = 0.f;
#pragma unroll
        for (int nf = 0; nf < 16; nf++) {
            sacc[nf][0] = ex2f(sacc[nf][0] - m0);
            sacc[nf][1] = ex2f(sacc[nf][1] - m0);
            sacc[nf][2] = ex2f(sacc[nf][2] - m1);
            sacc[nf][3] = ex2f(sacc[nf][3] - m1);
            rs0 += sacc[nf][0] + sacc[nf][1];
            rs1 += sacc[nf][2] + sacc[nf][3];
        }
        rs0 += __shfl_xor_sync(0xffffffffu, rs0, 1);
        rs0 += __shfl_xor_sync(0xffffffffu, rs0, 2);
        rs1 += __shfl_xor_sync(0xffffffffu, rs1, 1);
        rs1 += __shfl_xor_sync(0xffffffffu, rs1, 2);
        l0 = l0 * c0 + rs0;
        l1 = l1 * c1 + rs1;
#pragma unroll
        for (int nf = 0; nf < 8; nf++) {
            oacc[nf][0] *= c0; oacc[nf][1] *= c0;
            oacc[nf][2] *= c1; oacc[nf][3] *= c1;
        }

        // ---- O += P V (single fp16 term); P packed straight into A-frags ----
#pragma unroll
        for (int ks = 0; ks < 8; ks++) {
            uint32_t pf[4];
            pf[0] = pack_h16(sacc[2*ks][0],   sacc[2*ks][1]);
            pf[1] = pack_h16(sacc[2*ks][2],   sacc[2*ks][3]);
            pf[2] = pack_h16(sacc[2*ks+1][0], sacc[2*ks+1][1]);
            pf[3] = pack_h16(sacc[2*ks+1][2], sacc[2*ks+1][3]);
            const int rowV = ks * 16 + ((lid >> 3) & 1) * 8 + (lid & 7);
#pragma unroll
            for (int dv = 0; dv < 4; dv++) {
                const int ch = dv * 2 + (lid >> 4);
                const uint32_t off = rowV * 128 + ((ch ^ (rowV & 7)) << 4);
                uint32_t vf[4];
                ldsm4t(vf[0], vf[1], vf[2], vf[3], aV + off);
                mma_f16(oacc[2*dv],   pf, vf);
                mma_f16(oacc[2*dv+1], pf, vf + 2);
            }
        }
    }

    // ---- epilogue: AO[b][q][h*64+d] = O / l ----
    const float inv0 = 1.f / l0, inv1 = 1.f / l1;
    const int qa = q0 + wid * 16 + g;
#pragma unroll
    for (int nf = 0; nf < 8; nf++) {
        const int d = h * 64 + nf * 8 + t * 2;
        *(float2*)&AO[(size_t)(b * T_ + qa) * C_ + d] =
            make_float2(oacc[nf][0] * inv0, oacc[nf][1] * inv0);
        *(float2*)&AO[(size_t)(b * T_ + qa + 8) * C_ + d] =
            make_float2(oacc[nf][2] * inv1, oacc[nf][3] * inv1);
    }
}

// ---------------------------------------------------------------------------
extern "C" void kernel_launch(void* const* d_in, const int* in_sizes, int n_in,
                              void* d_out, int out_size)
{
    (void)in_sizes; (void)n_in; (void)out_size;
    const float* x1 = (const float*)d_in[0];
    const float* x2 = (const float*)d_in[1];
    const float* Wq = (const float*)d_in[2];
    const float* bq = (const float*)d_in[3];
    const float* Wk = (const float*)d_in[4];
    const float* bk = (const float*)d_in[5];
    const float* Wv = (const float*)d_in[6];
    const float* bv = (const float*)d_in[7];
    const float* Wu = (const float*)d_in[8];
    const float* bu = (const float*)d_in[9];
    float* out = (float*)d_out;

    __half *qf, *kf, *vf;
    float* aop;
    cudaGetSymbolAddress((void**)&qf, g_Qf);
    cudaGetSymbolAddress((void**)&kf, g_Kf);
    cudaGetSymbolAddress((void**)&vf, g_Vf);
    cudaGetSymbolAddress((void**)&aop, g_AO);

    cudaFuncSetAttribute(proj_mma<0>, cudaFuncAttributeMaxDynamicSharedMemorySize, PROJ_SMEM);
    cudaFuncSetAttribute(proj_mma<1>, cudaFuncAttributeMaxDynamicSharedMemorySize, PROJ_SMEM);
    cudaFuncSetAttribute(attn_mma,    cudaFuncAttributeMaxDynamicSharedMemorySize, ATT_SMEM);

    // Q scale: (1/sqrt(C)) * log2(e)  -> softmax in log2 domain
    const float SCALEQ = 0.03125f * 1.4426950408889634f;
    dim3 gp(C_ / 128, M_ / 128);    // (8, 64)
    proj_mma<0><<<gp, 256, PROJ_SMEM>>>(x1, Wq, bq, nullptr, qf, SCALEQ);
    proj_mma<0><<<gp, 256, PROJ_SMEM>>>(x2, Wk, bk, nullptr, kf, 1.f);
    proj_mma<0><<<gp, 256, PROJ_SMEM>>>(x2, Wv, bv, nullptr, vf, 1.f);
    attn_mma<<<dim3(T_ / 128, H_, B_), 256, ATT_SMEM>>>(qf, kf, vf, aop);
    proj_mma<1><<<gp, 256, PROJ_SMEM>>>(aop, Wu, bu, out, nullptr, 1.f);
}

// round 15
// speedup vs baseline: 1.2801x; 1.0016x over previous
#include <cuda_runtime.h>
#include <cuda_bf16.h>
#include <cuda_fp16.h>
#include <cstdint>

// ---------------------------------------------------------------------------
// MHA cross-attention.
//   proj q/k/v: bf16x3-split HMMA GEMM (fp32-grade), fp32 in -> fp16 out
//               scattered [b][h][t][d]; Q scale folds 1/sqrt(C) * log2(e).
//   attention:  fp16 single-term HMMA flash kernel, softmax in log2 domain.
//   out-proj:   bf16x3-split HMMA, fp32 out.
// ---------------------------------------------------------------------------

constexpr int T_  = 2048;
constexpr int B_  = 4;
constexpr int C_  = 1024;
constexpr int H_  = 16;
constexpr int HD_ = 64;
constexpr int M_  = T_ * B_;   // 8192 rows

// Scratch (device globals: allocation-free per harness rules).
__device__ __half g_Qf[M_ * C_];
__device__ __half g_Kf[M_ * C_];
__device__ __half g_Vf[M_ * C_];
__device__ float  g_AO[M_ * C_];

// ============================ helpers ======================================
__device__ __forceinline__ uint32_t smem_u32(const void* p) {
    uint32_t a;
    asm("{ .reg .u64 t; cvta.to.shared.u64 t, %1; cvt.u32.u64 %0, t; }"
        : "=r"(a) : "l"(p));
    return a;
}
__device__ __forceinline__ void ldsm4(uint32_t& r0, uint32_t& r1,
                                      uint32_t& r2, uint32_t& r3, uint32_t a) {
    asm volatile("ldmatrix.sync.aligned.m8n8.x4.shared.b16 {%0,%1,%2,%3}, [%4];"
                 : "=r"(r0), "=r"(r1), "=r"(r2), "=r"(r3) : "r"(a));
}
__device__ __forceinline__ void ldsm4t(uint32_t& r0, uint32_t& r1,
                                       uint32_t& r2, uint32_t& r3, uint32_t a) {
    asm volatile("ldmatrix.sync.aligned.m8n8.x4.trans.shared.b16 {%0,%1,%2,%3}, [%4];"
                 : "=r"(r0), "=r"(r1), "=r"(r2), "=r"(r3) : "r"(a));
}
__device__ __forceinline__ void mma_bf16(float* c, const uint32_t* a,
                                         const uint32_t* b) {
    asm volatile(
        "mma.sync.aligned.m16n8k16.row.col.f32.bf16.bf16.f32 "
        "{%0,%1,%2,%3}, {%4,%5,%6,%7}, {%8,%9}, {%0,%1,%2,%3};"
        : "+f"(c[0]), "+f"(c[1]), "+f"(c[2]), "+f"(c[3])
        : "r"(a[0]), "r"(a[1]), "r"(a[2]), "r"(a[3]), "r"(b[0]), "r"(b[1]));
}
__device__ __forceinline__ void mma_f16(float* c, const uint32_t* a,
                                        const uint32_t* b) {
    asm volatile(
        "mma.sync.aligned.m16n8k16.row.col.f32.f16.f16.f32 "
        "{%0,%1,%2,%3}, {%4,%5,%6,%7}, {%8,%9}, {%0,%1,%2,%3};"
        : "+f"(c[0]), "+f"(c[1]), "+f"(c[2]), "+f"(c[3])
        : "r"(a[0]), "r"(a[1]), "r"(a[2]), "r"(a[3]), "r"(b[0]), "r"(b[1]));
}
// pack two fp32 into bf16x2 / f16x2 (first arg -> low half)
__device__ __forceinline__ uint32_t pack_bf16(float lo, float hi) {
    uint32_t r;
    asm("cvt.rn.bf16x2.f32 %0, %1, %2;" : "=r"(r) : "f"(hi), "f"(lo));
    return r;
}
__device__ __forceinline__ uint32_t pack_h16(float lo, float hi) {
    uint32_t r;
    asm("cvt.rn.f16x2.f32 %0, %1, %2;" : "=r"(r) : "f"(hi), "f"(lo));
    return r;
}
__device__ __forceinline__ float ex2f(float x) {
    float y;
    asm("ex2.approx.f32 %0, %1;" : "=f"(y) : "f"(x));
    return y;
}
// split two fp32 into (hi-word, lo-word) bf16x2 pairs
__device__ __forceinline__ void split2(float a, float b, uint32_t& hw, uint32_t& lw) {
    float ha = __bfloat162float(__float2bfloat16_rn(a));
    float hb = __bfloat162float(__float2bfloat16_rn(b));
    hw = pack_bf16(a, b);
    lw = pack_bf16(a - ha, b - hb);
}
__device__ __forceinline__ void split4(float4 v, uint2& h, uint2& l) {
    split2(v.x, v.y, h.x, l.x);
    split2(v.z, v.w, h.y, l.y);
}

// ============================ projection ===================================
// Y = X(MxK) @ W^T(NxK) + bias,  bf16x3 split on mma.sync.
// Block tile 128x128, K-chunk 32 fp32. 8 warps, warp tile 64x32.
constexpr int PROJ_BUF  = 4 * 128 * 32 * 2;   // 32768 B
constexpr int PROJ_SMEM = 2 * PROJ_BUF;       // 65536 B (double buffered)

// MODE 0: write fp16 scattered to [b][h][t][d] (scale folded).
// MODE 1: write fp32 Y[r*C+n].
template <int MODE>
__global__ void __launch_bounds__(256, 1) proj_mma(
    const float* __restrict__ X, const float* __restrict__ W,
    const float* __restrict__ bias, float* __restrict__ Yf,
    __half* __restrict__ Yh, float scale)
{
    extern __shared__ char smem[];
    const uint32_t sbase = smem_u32(smem);
    const int tid = threadIdx.x;
    const int wid = tid >> 5;
    const int lid = tid & 31;
    const int bm  = blockIdx.y * 128;
    const int bn  = blockIdx.x * 128;

    const int wm = wid & 1;
    const int wn = wid >> 1;

    const int rA = lid & 15;
    const int cA = lid >> 4;
    const int rB = ((lid >> 4) << 3) + (lid & 7);
    const int cB = (lid >> 3) & 1;

    int grow[4], gc4[4];
#pragma unroll
    for (int i = 0; i < 4; i++) {
        const int f = tid + i * 256;
        grow[i] = f >> 3;
        gc4[i]  = f & 7;
    }

    float acc[4][4][4];
#pragma unroll
    for (int mf = 0; mf < 4; mf++)
#pragma unroll
        for (int nf = 0; nf < 4; nf++)
#pragma unroll
            for (int j = 0; j < 4; j++) acc[mf][nf][j] = 0.f;

    float4 ga[4], gb[4];

    auto load_regs = [&](int kt) {
#pragma unroll
        for (int i = 0; i < 4; i++) {
            ga[i] = *(const float4*)(X + (size_t)(bm + grow[i]) * C_ + kt * 32 + gc4[i] * 4);
            gb[i] = *(const float4*)(W + (size_t)(bn + grow[i]) * C_ + kt * 32 + gc4[i] * 4);
        }
    };
    auto store_split = [&](char* buf) {
#pragma unroll
        for (int i = 0; i < 4; i++) {
            const int row = grow[i], c4 = gc4[i];
            const uint32_t o = row * 64 +
                ((((c4 >> 1) ^ ((row >> 1) & 3))) << 4) + (c4 & 1) * 8;
            uint2 h, l;
            split4(ga[i], h, l);
            *(uint2*)(buf + o)         = h;
            *(uint2*)(buf + 8192 + o)  = l;
            split4(gb[i], h, l);
            *(uint2*)(buf + 16384 + o) = h;
            *(uint2*)(buf + 24576 + o) = l;
        }
    };
    auto compute = [&](uint32_t bb) {
        const uint32_t ahi = bb, alo = bb + 8192, bhi = bb + 16384, blo = bb + 24576;
#pragma unroll
        for (int ks = 0; ks < 2; ks++) {
            uint32_t bh[4][2], bl[4][2];
#pragma unroll
            for (int p = 0; p < 2; p++) {
                const int rowB = wn * 32 + p * 16 + rB;
                const uint32_t off = rowB * 64 +
                    (((ks * 2 + cB) ^ ((rowB >> 1) & 3)) << 4);
                ldsm4(bh[2*p][0], bh[2*p][1], bh[2*p+1][0], bh[2*p+1][1], bhi + off);
                ldsm4(bl[2*p][0], bl[2*p][1], bl[2*p+1][0], bl[2*p+1][1], blo + off);
            }
#pragma unroll
            for (int mf = 0; mf < 4; mf++) {
                const int rowA = wm * 64 + mf * 16 + rA;
                const uint32_t off = rowA * 64 +
                    (((ks * 2 + cA) ^ ((rowA >> 1) & 3)) << 4);
                uint32_t ah[4], al[4];
                ldsm4(ah[0], ah[1], ah[2], ah[3], ahi + off);
                ldsm4(al[0], al[1], al[2], al[3], alo + off);
#pragma unroll
                for (int nf = 0; nf < 4; nf++) {
                    mma_bf16(acc[mf][nf], ah, bh[nf]);
                    mma_bf16(acc[mf][nf], ah, bl[nf]);
                    mma_bf16(acc[mf][nf], al, bh[nf]);
                }
            }
        }
    };

    load_regs(0);
    store_split(smem);
    __syncthreads();
    int cur = 0;
    const int NCHUNK = C_ / 32;
    for (int kt = 0; kt < NCHUNK; kt++) {
        const bool has_next = (kt + 1) < NCHUNK;
        if (has_next) load_regs(kt + 1);
        compute(sbase + cur * PROJ_BUF);
        if (has_next) {
            store_split(smem + (cur ^ 1) * PROJ_BUF);
            __syncthreads();
            cur ^= 1;
        }
    }

#pragma unroll
    for (int mf = 0; mf < 4; mf++) {
        const int m = bm + wm * 64 + mf * 16 + (lid >> 2);
#pragma unroll
        for (int nf = 0; nf < 4; nf++) {
            const int n0 = bn + wn * 32 + nf * 8 + (lid & 3) * 2;
            const float2 bb = *(const float2*)(bias + n0);
            float v00 = acc[mf][nf][0] + bb.x, v01 = acc[mf][nf][1] + bb.y;
            float v10 = acc[mf][nf][2] + bb.x, v11 = acc[mf][nf][3] + bb.y;
            if (MODE == 0) {
                v00 *= scale; v01 *= scale; v10 *= scale; v11 *= scale;
                const int h = n0 >> 6, d = n0 & 63;
                int t = m >> 2, b2 = m & 3;
                size_t idx = ((size_t)(b2 * H_ + h) * T_ + t) * HD_ + d;
                *(uint32_t*)(Yh + idx) = pack_h16(v00, v01);
                t = (m + 8) >> 2; b2 = (m + 8) & 3;
                idx = ((size_t)(b2 * H_ + h) * T_ + t) * HD_ + d;
                *(uint32_t*)(Yh + idx) = pack_h16(v10, v11);
            } else {
                *(float2*)&Yf[(size_t)m * C_ + n0]       = make_float2(v00, v01);
                *(float2*)&Yf[(size_t)(m + 8) * C_ + n0] = make_float2(v10, v11);
            }
        }
    }
}

// ============================ flash attention (fp16 HMMA) ==================
// CTA: 128 queries of one (b,h). 8 warps x 16 queries. K-tiles of 128 keys.
// smem: Q K V, each [128][64] fp16 = 16KB (128B rows, XOR swizzle
// off = r*128 + ((chunk ^ (r&7))<<4)).  Total 48KB.
// Q pre-scaled by (1/sqrt(C))*log2(e): softmax runs in log2 domain (ex2).
constexpr int ATT_SMEM = 3 * 16384;

__global__ void __launch_bounds__(256, 1) attn_mma(
    const __half* __restrict__ Qf, const __half* __restrict__ Kf,
    const __half* __restrict__ Vf, float* __restrict__ AO)
{
    extern __shared__ char sm[];
    const uint32_t aQ = smem_u32(sm);
    const uint32_t aK = aQ + 16384;
    const uint32_t aV = aQ + 32768;

    const int tid = threadIdx.x, wid = tid >> 5, lid = tid & 31;
    const int g = lid >> 2, t = lid & 3;
    const int b = blockIdx.z, h = blockIdx.y, q0 = blockIdx.x * 128;
    const size_t base = (size_t)(b * H_ + h) * T_ * HD_;

    // ---- load Q tile (once) ----
    for (int i = tid; i < 1024; i += 256) {
        const int r = i >> 3, c = i & 7;
        const uint32_t off = r * 128 + ((c ^ (r & 7)) << 4);
        *(uint4*)(sm + off) =
            *(const uint4*)((const char*)(Qf + base + (size_t)(q0 + r) * HD_) + c * 16);
    }
    __syncthreads();

    // Q fragments in registers for the whole kernel
    uint32_t qf[4][4];
    {
        const int rowA = wid * 16 + (lid & 15);
#pragma unroll
        for (int ks = 0; ks < 4; ks++) {
            const int ch = ks * 2 + (lid >> 4);
            const uint32_t off = rowA * 128 + ((ch ^ (rowA & 7)) << 4);
            ldsm4(qf[ks][0], qf[ks][1], qf[ks][2], qf[ks][3], aQ + off);
        }
    }

    float oacc[8][4];
#pragma unroll
    for (int nf = 0; nf < 8; nf++)
#pragma unroll
        for (int j = 0; j < 4; j++) oacc[nf][j] = 0.f;
    float m0 = -1e30f, m1 = -1e30f, l0 = 0.f, l1 = 0.f;

    for (int kt = 0; kt < 16; kt++) {
        const int k0 = kt * 128;
        __syncthreads();   // previous tile's K/V reads done
        for (int i = tid; i < 1024; i += 256) {
            const int r = i >> 3, c = i & 7;
            const uint32_t off = r * 128 + ((c ^ (r & 7)) << 4);
            const size_t go = base + (size_t)(k0 + r) * HD_;
            *(uint4*)(sm + 16384 + off) = *(const uint4*)((const char*)(Kf + go) + c * 16);
            *(uint4*)(sm + 32768 + off) = *(const uint4*)((const char*)(Vf + go) + c * 16);
        }
        __syncthreads();

        // ---- S = Q K^T (single fp16 term; S already in log2 units) ----
        float sacc[16][4];
#pragma unroll
        for (int nf = 0; nf < 16; nf++)
#pragma unroll
            for (int j = 0; j < 4; j++) sacc[nf][j] = 0.f;

#pragma unroll
        for (int ks = 0; ks < 4; ks++) {
#pragma unroll
            for (int p = 0; p < 8; p++) {
                const int rowB = p * 16 + ((lid >> 4) << 3) + (lid & 7);
                const int ch = ks * 2 + ((lid >> 3) & 1);
                const uint32_t off = rowB * 128 + ((ch ^ (rowB & 7)) << 4);
                uint32_t kfrag[4];
                ldsm4(kfrag[0], kfrag[1], kfrag[2], kfrag[3], aK + off);
                mma_f16(sacc[2*p],   qf[ks], kfrag);
                mma_f16(sacc[2*p+1], qf[ks], kfrag + 2);
            }
        }

        // ---- online softmax in log2 domain (rows g, g+8; warp-local) ----
        float rmax0 = -1e30f, rmax1 = -1e30f;
#pragma unroll
        for (int nf = 0; nf < 16; nf++) {
            rmax0 = fmaxf(rmax0, fmaxf(sacc[nf][0], sacc[nf][1]));
            rmax1 = fmaxf(rmax1, fmaxf(sacc[nf][2], sacc[nf][3]));
        }
        rmax0 = fmaxf(rmax0, __shfl_xor_sync(0xffffffffu, rmax0, 1));
        rmax0 = fmaxf(rmax0, __shfl_xor_sync(0xffffffffu, rmax0, 2));
        rmax1 = fmaxf(rmax1, __shfl_xor_sync(0xffffffffu, rmax1, 1));
        rmax1 = fmaxf(rmax1, __shfl_xor_sync(0xffffffffu, rmax1, 2));
        const float mn0 = fmaxf(m0, rmax0), mn1 = fmaxf(m1, rmax1);
        const float c0 = ex2f(m0 - mn0), c1 = ex2f(m1 - mn1);
        m0 = mn0; m1 = mn1;
        float rs0 = 0.f, rs1 = 0.f;
#pragma unroll
        for (int nf = 0; nf < 16; nf++) {
            sacc[nf][0] = ex2f(sacc[nf][0] - m0);
            sacc[nf][1] = ex2f(sacc[nf][1] - m0);
            sacc[nf][2] = ex2f(sacc[nf][2] - m1);
            sacc[nf][3] = ex2f(sacc[nf][3] - m1);
            rs0 += sacc[nf][0] + sacc[nf][1];
            rs1 += sacc[nf][2] + sacc[nf][3];
        }
        rs0 += __shfl_xor_sync(0xffffffffu, rs0, 1);
        rs0 += __shfl_xor_sync(0xffffffffu, rs0, 2);
        rs1 += __shfl_xor_sync(0xffffffffu, rs1, 1);
        rs1 += __shfl_xor_sync(0xffffffffu, rs1, 2);
        l0 = l0 * c0 + rs0;
        l1 = l1 * c1 + rs1;
#pragma unroll
        for (int nf = 0; nf < 8; nf++) {
            oacc[nf][0] *= c0; oacc[nf][1] *= c0;
            oacc[nf][2] *= c1; oacc[nf][3] *= c1;
        }

        // ---- O += P V (single fp16 term); P packed straight into A-frags ----
#pragma unroll
        for (int ks = 0; ks < 8; ks++) {
            uint32_t pf[4];
            pf[0] = pack_h16(sacc[2*ks][0],   sacc[2*ks][1]);
            pf[1] = pack_h16(sacc[2*ks][2],   sacc[2*ks][3]);
            pf[2] = pack_h16(sacc[2*ks+1][0], sacc[2*ks+1][1]);
            pf[3] = pack_h16(sacc[2*ks+1][2], sacc[2*ks+1][3]);
            const int rowV = ks * 16 + ((lid >> 3) & 1) * 8 + (lid & 7);
#pragma unroll
            for (int dv = 0; dv < 4; dv++) {
                const int ch = dv * 2 + (lid >> 4);
                const uint32_t off = rowV * 128 + ((ch ^ (rowV & 7)) << 4);
                uint32_t vf[4];
                ldsm4t(vf[0], vf[1], vf[2], vf[3], aV + off);
                mma_f16(oacc[2*dv],   pf, vf);
                mma_f16(oacc[2*dv+1], pf, vf + 2);
            }
        }
    }

    // ---- epilogue: AO[b][q][h*64+d] = O / l ----
    const float inv0 = 1.f / l0, inv1 = 1.f / l1;
    const int qa = q0 + wid * 16 + g;
#pragma unroll
    for (int nf = 0; nf < 8; nf++) {
        const int d = h * 64 + nf * 8 + t * 2;
        *(float2*)&AO[(size_t)(b * T_ + qa) * C_ + d] =
            make_float2(oacc[nf][0] * inv0, oacc[nf][1] * inv0);
        *(float2*)&AO[(size_t)(b * T_ + qa + 8) * C_ + d] =
            make_float2(oacc[nf][2] * inv1, oacc[nf][3] * inv1);
    }
}

// ---------------------------------------------------------------------------
extern "C" void kernel_launch(void* const* d_in, const int* in_sizes, int n_in,
                              void* d_out, int out_size)
{
    (void)in_sizes; (void)n_in; (void)out_size;
    const float* x1 = (const float*)d_in[0];
    const float* x2 = (const float*)d_in[1];
    const float* Wq = (const float*)d_in[2];
    const float* bq = (const float*)d_in[3];
    const float* Wk = (const float*)d_in[4];
    const float* bk = (const float*)d_in[5];
    const float* Wv = (const float*)d_in[6];
    const float* bv = (const float*)d_in[7];
    const float* Wu = (const float*)d_in[8];
    const float* bu = (const float*)d_in[9];
    float* out = (float*)d_out;

    __half *qf, *kf, *vf;
    float* aop;
    cudaGetSymbolAddress((void**)&qf, g_Qf);
    cudaGetSymbolAddress((void**)&kf, g_Kf);
    cudaGetSymbolAddress((void**)&vf, g_Vf);
    cudaGetSymbolAddress((void**)&aop, g_AO);

    cudaFuncSetAttribute(proj_mma<0>, cudaFuncAttributeMaxDynamicSharedMemorySize, PROJ_SMEM);
    cudaFuncSetAttribute(proj_mma<1>, cudaFuncAttributeMaxDynamicSharedMemorySize, PROJ_SMEM);
    cudaFuncSetAttribute(attn_mma,    cudaFuncAttributeMaxDynamicSharedMemorySize, ATT_SMEM);

    // Q scale: (1/sqrt(C)) * log2(e)  -> softmax in log2 domain
    const float SCALEQ = 0.03125f * 1.4426950408889634f;
    dim3 gp(C_ / 128, M_ / 128);    // (8, 64)
    proj_mma<0><<<gp, 256, PROJ_SMEM>>>(x1, Wq, bq, nullptr, qf, SCALEQ);
    proj_mma<0><<<gp, 256, PROJ_SMEM>>>(x2, Wk, bk, nullptr, kf, 1.f);
    proj_mma<0><<<gp, 256, PROJ_SMEM>>>(x2, Wv, bv, nullptr, vf, 1.f);
    attn_mma<<<dim3(T_ / 128, H_, B_), 256, ATT_SMEM>>>(qf, kf, vf, aop);
    proj_mma<1><<<gp, 256, PROJ_SMEM>>>(aop, Wu, bu, out, nullptr, 1.f);
}

// round 16
// speedup vs baseline: 1.2809x; 1.0006x over previous
#include <cuda_runtime.h>
#include <cuda_bf16.h>
#include <cuda_fp16.h>
#include <cstdint>

// ---------------------------------------------------------------------------
// MHA cross-attention.
//   proj q/k/v: bf16x3-split HMMA GEMM (fp32-grade), fp32 in -> fp16 out
//               scattered [b][h][t][d]; Q scale folds 1/sqrt(C) * log2(e).
//   attention:  fp16 single-term HMMA flash kernel, softmax in log2 domain.
//   out-proj:   bf16x3-split HMMA, fp32 out.
// ---------------------------------------------------------------------------

constexpr int T_  = 2048;
constexpr int B_  = 4;
constexpr int C_  = 1024;
constexpr int H_  = 16;
constexpr int HD_ = 64;
constexpr int M_  = T_ * B_;   // 8192 rows

// Scratch (device globals: allocation-free per harness rules).
__device__ __half g_Qf[M_ * C_];
__device__ __half g_Kf[M_ * C_];
__device__ __half g_Vf[M_ * C_];
__device__ float  g_AO[M_ * C_];

// ============================ helpers ======================================
__device__ __forceinline__ uint32_t smem_u32(const void* p) {
    uint32_t a;
    asm("{ .reg .u64 t; cvta.to.shared.u64 t, %1; cvt.u32.u64 %0, t; }"
        : "=r"(a) : "l"(p));
    return a;
}
__device__ __forceinline__ void ldsm4(uint32_t& r0, uint32_t& r1,
                                      uint32_t& r2, uint32_t& r3, uint32_t a) {
    asm volatile("ldmatrix.sync.aligned.m8n8.x4.shared.b16 {%0,%1,%2,%3}, [%4];"
                 : "=r"(r0), "=r"(r1), "=r"(r2), "=r"(r3) : "r"(a));
}
__device__ __forceinline__ void ldsm4t(uint32_t& r0, uint32_t& r1,
                                       uint32_t& r2, uint32_t& r3, uint32_t a) {
    asm volatile("ldmatrix.sync.aligned.m8n8.x4.trans.shared.b16 {%0,%1,%2,%3}, [%4];"
                 : "=r"(r0), "=r"(r1), "=r"(r2), "=r"(r3) : "r"(a));
}
__device__ __forceinline__ void mma_bf16(float* c, const uint32_t* a,
                                         const uint32_t* b) {
    asm volatile(
        "mma.sync.aligned.m16n8k16.row.col.f32.bf16.bf16.f32 "
        "{%0,%1,%2,%3}, {%4,%5,%6,%7}, {%8,%9}, {%0,%1,%2,%3};"
        : "+f"(c[0]), "+f"(c[1]), "+f"(c[2]), "+f"(c[3])
        : "r"(a[0]), "r"(a[1]), "r"(a[2]), "r"(a[3]), "r"(b[0]), "r"(b[1]));
}
__device__ __forceinline__ void mma_f16(float* c, const uint32_t* a,
                                        const uint32_t* b) {
    asm volatile(
        "mma.sync.aligned.m16n8k16.row.col.f32.f16.f16.f32 "
        "{%0,%1,%2,%3}, {%4,%5,%6,%7}, {%8,%9}, {%0,%1,%2,%3};"
        : "+f"(c[0]), "+f"(c[1]), "+f"(c[2]), "+f"(c[3])
        : "r"(a[0]), "r"(a[1]), "r"(a[2]), "r"(a[3]), "r"(b[0]), "r"(b[1]));
}
// pack two fp32 into bf16x2 / f16x2 (first arg -> low half)
__device__ __forceinline__ uint32_t pack_bf16(float lo, float hi) {
    uint32_t r;
    asm("cvt.rn.bf16x2.f32 %0, %1, %2;" : "=r"(r) : "f"(hi), "f"(lo));
    return r;
}
__device__ __forceinline__ uint32_t pack_h16(float lo, float hi) {
    uint32_t r;
    asm("cvt.rn.f16x2.f32 %0, %1, %2;" : "=r"(r) : "f"(hi), "f"(lo));
    return r;
}
__device__ __forceinline__ float ex2f(float x) {
    float y;
    asm("ex2.approx.f32 %0, %1;" : "=f"(y) : "f"(x));
    return y;
}
// split two fp32 into (hi-word, lo-word) bf16x2 pairs
__device__ __forceinline__ void split2(float a, float b, uint32_t& hw, uint32_t& lw) {
    float ha = __bfloat162float(__float2bfloat16_rn(a));
    float hb = __bfloat162float(__float2bfloat16_rn(b));
    hw = pack_bf16(a, b);
    lw = pack_bf16(a - ha, b - hb);
}
__device__ __forceinline__ void split4(float4 v, uint2& h, uint2& l) {
    split2(v.x, v.y, h.x, l.x);
    split2(v.z, v.w, h.y, l.y);
}

// ============================ projection ===================================
// Y = X(MxK) @ W^T(NxK) + bias,  bf16x3 split on mma.sync.
// Block tile 128x128, K-chunk 32 fp32. 8 warps, warp tile 64x32.
constexpr int PROJ_BUF  = 4 * 128 * 32 * 2;   // 32768 B
constexpr int PROJ_SMEM = 2 * PROJ_BUF;       // 65536 B (double buffered)

// MODE 0: write fp16 scattered to [b][h][t][d] (scale folded).
// MODE 1: write fp32 Y[r*C+n].
template <int MODE>
__global__ void __launch_bounds__(256, 1) proj_mma(
    const float* __restrict__ X, const float* __restrict__ W,
    const float* __restrict__ bias, float* __restrict__ Yf,
    __half* __restrict__ Yh, float scale)
{
    extern __shared__ char smem[];
    const uint32_t sbase = smem_u32(smem);
    const int tid = threadIdx.x;
    const int wid = tid >> 5;
    const int lid = tid & 31;
    const int bm  = blockIdx.y * 128;
    const int bn  = blockIdx.x * 128;

    const int wm = wid & 1;
    const int wn = wid >> 1;

    const int rA = lid & 15;
    const int cA = lid >> 4;
    const int rB = ((lid >> 4) << 3) + (lid & 7);
    const int cB = (lid >> 3) & 1;

    int grow[4], gc4[4];
#pragma unroll
    for (int i = 0; i < 4; i++) {
        const int f = tid + i * 256;
        grow[i] = f >> 3;
        gc4[i]  = f & 7;
    }

    float acc[4][4][4];
#pragma unroll
    for (int mf = 0; mf < 4; mf++)
#pragma unroll
        for (int nf = 0; nf < 4; nf++)
#pragma unroll
            for (int j = 0; j < 4; j++) acc[mf][nf][j] = 0.f;

    float4 ga[4], gb[4];

    auto load_regs = [&](int kt) {
#pragma unroll
        for (int i = 0; i < 4; i++) {
            ga[i] = *(const float4*)(X + (size_t)(bm + grow[i]) * C_ + kt * 32 + gc4[i] * 4);
            gb[i] = *(const float4*)(W + (size_t)(bn + grow[i]) * C_ + kt * 32 + gc4[i] * 4);
        }
    };
    auto store_split = [&](char* buf) {
#pragma unroll
        for (int i = 0; i < 4; i++) {
            const int row = grow[i], c4 = gc4[i];
            const uint32_t o = row * 64 +
                ((((c4 >> 1) ^ ((row >> 1) & 3))) << 4) + (c4 & 1) * 8;
            uint2 h, l;
            split4(ga[i], h, l);
            *(uint2*)(buf + o)         = h;
            *(uint2*)(buf + 8192 + o)  = l;
            split4(gb[i], h, l);
            *(uint2*)(buf + 16384 + o) = h;
            *(uint2*)(buf + 24576 + o) = l;
        }
    };
    auto compute = [&](uint32_t bb) {
        const uint32_t ahi = bb, alo = bb + 8192, bhi = bb + 16384, blo = bb + 24576;
#pragma unroll
        for (int ks = 0; ks < 2; ks++) {
            uint32_t bh[4][2], bl[4][2];
#pragma unroll
            for (int p = 0; p < 2; p++) {
                const int rowB = wn * 32 + p * 16 + rB;
                const uint32_t off = rowB * 64 +
                    (((ks * 2 + cB) ^ ((rowB >> 1) & 3)) << 4);
                ldsm4(bh[2*p][0], bh[2*p][1], bh[2*p+1][0], bh[2*p+1][1], bhi + off);
                ldsm4(bl[2*p][0], bl[2*p][1], bl[2*p+1][0], bl[2*p+1][1], blo + off);
            }
#pragma unroll
            for (int mf = 0; mf < 4; mf++) {
                const int rowA = wm * 64 + mf * 16 + rA;
                const uint32_t off = rowA * 64 +
                    (((ks * 2 + cA) ^ ((rowA >> 1) & 3)) << 4);
                uint32_t ah[4], al[4];
                ldsm4(ah[0], ah[1], ah[2], ah[3], ahi + off);
                ldsm4(al[0], al[1], al[2], al[3], alo + off);
#pragma unroll
                for (int nf = 0; nf < 4; nf++) {
                    mma_bf16(acc[mf][nf], ah, bh[nf]);
                    mma_bf16(acc[mf][nf], ah, bl[nf]);
                    mma_bf16(acc[mf][nf], al, bh[nf]);
                }
            }
        }
    };

    load_regs(0);
    store_split(smem);
    __syncthreads();
    int cur = 0;
    const int NCHUNK = C_ / 32;
    for (int kt = 0; kt < NCHUNK; kt++) {
        const bool has_next = (kt + 1) < NCHUNK;
        if (has_next) load_regs(kt + 1);
        compute(sbase + cur * PROJ_BUF);
        if (has_next) {
            store_split(smem + (cur ^ 1) * PROJ_BUF);
            __syncthreads();
            cur ^= 1;
        }
    }

#pragma unroll
    for (int mf = 0; mf < 4; mf++) {
        const int m = bm + wm * 64 + mf * 16 + (lid >> 2);
#pragma unroll
        for (int nf = 0; nf < 4; nf++) {
            const int n0 = bn + wn * 32 + nf * 8 + (lid & 3) * 2;
            const float2 bb = *(const float2*)(bias + n0);
            float v00 = acc[mf][nf][0] + bb.x, v01 = acc[mf][nf][1] + bb.y;
            float v10 = acc[mf][nf][2] + bb.x, v11 = acc[mf][nf][3] + bb.y;
            if (MODE == 0) {
                v00 *= scale; v01 *= scale; v10 *= scale; v11 *= scale;
                const int h = n0 >> 6, d = n0 & 63;
                int t = m >> 2, b2 = m & 3;
                size_t idx = ((size_t)(b2 * H_ + h) * T_ + t) * HD_ + d;
                *(uint32_t*)(Yh + idx) = pack_h16(v00, v01);
                t = (m + 8) >> 2; b2 = (m + 8) & 3;
                idx = ((size_t)(b2 * H_ + h) * T_ + t) * HD_ + d;
                *(uint32_t*)(Yh + idx) = pack_h16(v10, v11);
            } else {
                *(float2*)&Yf[(size_t)m * C_ + n0]       = make_float2(v00, v01);
                *(float2*)&Yf[(size_t)(m + 8) * C_ + n0] = make_float2(v10, v11);
            }
        }
    }
}

// ============================ flash attention (fp16 HMMA) ==================
// CTA: 128 queries of one (b,h). 8 warps x 16 queries. K-tiles of 128 keys.
// smem: Q K V, each [128][64] fp16 = 16KB (128B rows, XOR swizzle
// off = r*128 + ((chunk ^ (r&7))<<4)).  Total 48KB.
// Q pre-scaled by (1/sqrt(C))*log2(e): softmax runs in log2 domain (ex2).
constexpr int ATT_SMEM = 3 * 16384;

__global__ void __launch_bounds__(256, 1) attn_mma(
    const __half* __restrict__ Qf, const __half* __restrict__ Kf,
    const __half* __restrict__ Vf, float* __restrict__ AO)
{
    extern __shared__ char sm[];
    const uint32_t aQ = smem_u32(sm);
    const uint32_t aK = aQ + 16384;
    const uint32_t aV = aQ + 32768;

    const int tid = threadIdx.x, wid = tid >> 5, lid = tid & 31;
    const int g = lid >> 2, t = lid & 3;
    const int b = blockIdx.z, h = blockIdx.y, q0 = blockIdx.x * 128;
    const size_t base = (size_t)(b * H_ + h) * T_ * HD_;

    // ---- load Q tile (once) ----
    for (int i = tid; i < 1024; i += 256) {
        const int r = i >> 3, c = i & 7;
        const uint32_t off = r * 128 + ((c ^ (r & 7)) << 4);
        *(uint4*)(sm + off) =
            *(const uint4*)((const char*)(Qf + base + (size_t)(q0 + r) * HD_) + c * 16);
    }
    __syncthreads();

    // Q fragments in registers for the whole kernel
    uint32_t qf[4][4];
    {
        const int rowA = wid * 16 + (lid & 15);
#pragma unroll
        for (int ks = 0; ks < 4; ks++) {
            const int ch = ks * 2 + (lid >> 4);
            const uint32_t off = rowA * 128 + ((ch ^ (rowA & 7)) << 4);
            ldsm4(qf[ks][0], qf[ks][1], qf[ks][2], qf[ks][3], aQ + off);
        }
    }

    float oacc[8][4];
#pragma unroll
    for (int nf = 0; nf < 8; nf++)
#pragma unroll
        for (int j = 0; j < 4; j++) oacc[nf][j] = 0.f;
    float m0 = -1e30f, m1 = -1e30f, l0 = 0.f, l1 = 0.f;

    for (int kt = 0; kt < 16; kt++) {
        const int k0 = kt * 128;
        __syncthreads();   // previous tile's K/V reads done
        for (int i = tid; i < 1024; i += 256) {
            const int r = i >> 3, c = i & 7;
            const uint32_t off = r * 128 + ((c ^ (r & 7)) << 4);
            const size_t go = base + (size_t)(k0 + r) * HD_;
            *(uint4*)(sm + 16384 + off) = *(const uint4*)((const char*)(Kf + go) + c * 16);
            *(uint4*)(sm + 32768 + off) = *(const uint4*)((const char*)(Vf + go) + c * 16);
        }
        __syncthreads();

        // ---- S = Q K^T (single fp16 term; S already in log2 units) ----
        float sacc[16][4];
#pragma unroll
        for (int nf = 0; nf < 16; nf++)
#pragma unroll
            for (int j = 0; j < 4; j++) sacc[nf][j] = 0.f;

#pragma unroll
        for (int ks = 0; ks < 4; ks++) {
#pragma unroll
            for (int p = 0; p < 8; p++) {
                const int rowB = p * 16 + ((lid >> 4) << 3) + (lid & 7);
                const int ch = ks * 2 + ((lid >> 3) & 1);
                const uint32_t off = rowB * 128 + ((ch ^ (rowB & 7)) << 4);
                uint32_t kfrag[4];
                ldsm4(kfrag[0], kfrag[1], kfrag[2], kfrag[3], aK + off);
                mma_f16(sacc[2*p],   qf[ks], kfrag);
                mma_f16(sacc[2*p+1], qf[ks], kfrag + 2);
            }
        }

        // ---- online softmax in log2 domain (rows g, g+8; warp-local) ----
        float rmax0 = -1e30f, rmax1 = -1e30f;
#pragma unroll
        for (int nf = 0; nf < 16; nf++) {
            rmax0 = fmaxf(rmax0, fmaxf(sacc[nf][0], sacc[nf][1]));
            rmax1 = fmaxf(rmax1, fmaxf(sacc[nf][2], sacc[nf][3]));
        }
        rmax0 = fmaxf(rmax0, __shfl_xor_sync(0xffffffffu, rmax0, 1));
        rmax0 = fmaxf(rmax0, __shfl_xor_sync(0xffffffffu, rmax0, 2));
        rmax1 = fmaxf(rmax1, __shfl_xor_sync(0xffffffffu, rmax1, 1));
        rmax1 = fmaxf(rmax1, __shfl_xor_sync(0xffffffffu, rmax1, 2));
        const float mn0 = fmaxf(m0, rmax0), mn1 = fmaxf(m1, rmax1);
        const float c0 = ex2f(m0 - mn0), c1 = ex2f(m1 - mn1);
        m0 = mn0; m1 = mn1;
        float rs0 = 0.f, rs1 = 0.f;
#pragma unroll
        for (int nf = 0; nf < 16; nf++) {
            sacc[nf][0] = ex2f(sacc[nf][0] - m0);
            sacc[nf][1] = ex2f(sacc[nf][1] - m0);
            sacc[nf][2] = ex2f(sacc[nf][2] - m1);
            sacc[nf][3] = ex2f(sacc[nf][3] - m1);
            rs0 += sacc[nf][0] + sacc[nf][1];
            rs1 += sacc[nf][2] + sacc[nf][3];
        }
        rs0 += __shfl_xor_sync(0xffffffffu, rs0, 1);
        rs0 += __shfl_xor_sync(0xffffffffu, rs0, 2);
        rs1 += __shfl_xor_sync(0xffffffffu, rs1, 1);
        rs1 += __shfl_xor_sync(0xffffffffu, rs1, 2);
        l0 = l0 * c0 + rs0;
        l1 = l1 * c1 + rs1;
#pragma unroll
        for (int nf = 0; nf < 8; nf++) {
            oacc[nf][0] *= c0; oacc[nf][1] *= c0;
            oacc[nf][2] *= c1; oacc[nf][3] *= c1;
        }

        // ---- O += P V (single fp16 term); P packed straight into A-frags ----
#pragma unroll
        for (int ks = 0; ks < 8; ks++) {
            uint32_t pf[4];
            pf[0] = pack_h16(sacc[2*ks][0],   sacc[2*ks][1]);
            pf[1] = pack_h16(sacc[2*ks][2],   sacc[2*ks][3]);
            pf[2] = pack_h16(sacc[2*ks+1][0], sacc[2*ks+1][1]);
            pf[3] = pack_h16(sacc[2*ks+1][2], sacc[2*ks+1][3]);
            const int rowV = ks * 16 + ((lid >> 3) & 1) * 8 + (lid & 7);
#pragma unroll
            for (int dv = 0; dv < 4; dv++) {
                const int ch = dv * 2 + (lid >> 4);
                const uint32_t off = rowV * 128 + ((ch ^ (rowV & 7)) << 4);
                uint32_t vf[4];
                ldsm4t(vf[0], vf[1], vf[2], vf[3], aV + off);
                mma_f16(oacc[2*dv],   pf, vf);
                mma_f16(oacc[2*dv+1], pf, vf + 2);
            }
        }
    }

    // ---- epilogue: AO[b][q][h*64+d] = O / l ----
    const float inv0 = 1.f / l0, inv1 = 1.f / l1;
    const int qa = q0 + wid * 16 + g;
#pragma unroll
    for (int nf = 0; nf < 8; nf++) {
        const int d = h * 64 + nf * 8 + t * 2;
        *(float2*)&AO[(size_t)(b * T_ + qa) * C_ + d] =
            make_float2(oacc[nf][0] * inv0, oacc[nf][1] * inv0);
        *(float2*)&AO[(size_t)(b * T_ + qa + 8) * C_ + d] =
            make_float2(oacc[nf][2] * inv1, oacc[nf][3] * inv1);
    }
}

// ---------------------------------------------------------------------------
extern "C" void kernel_launch(void* const* d_in, const int* in_sizes, int n_in,
                              void* d_out, int out_size)
{
    (void)in_sizes; (void)n_in; (void)out_size;
    const float* x1 = (const float*)d_in[0];
    const float* x2 = (const float*)d_in[1];
    const float* Wq = (const float*)d_in[2];
    const float* bq = (const float*)d_in[3];
    const float* Wk = (const float*)d_in[4];
    const float* bk = (const float*)d_in[5];
    const float* Wv = (const float*)d_in[6];
    const float* bv = (const float*)d_in[7];
    const float* Wu = (const float*)d_in[8];
    const float* bu = (const float*)d_in[9];
    float* out = (float*)d_out;

    __half *qf, *kf, *vf;
    float* aop;
    cudaGetSymbolAddress((void**)&qf, g_Qf);
    cudaGetSymbolAddress((void**)&kf, g_Kf);
    cudaGetSymbolAddress((void**)&vf, g_Vf);
    cudaGetSymbolAddress((void**)&aop, g_AO);

    cudaFuncSetAttribute(proj_mma<0>, cudaFuncAttributeMaxDynamicSharedMemorySize, PROJ_SMEM);
    cudaFuncSetAttribute(proj_mma<1>, cudaFuncAttributeMaxDynamicSharedMemorySize, PROJ_SMEM);
    cudaFuncSetAttribute(attn_mma,    cudaFuncAttributeMaxDynamicSharedMemorySize, ATT_SMEM);

    // Q scale: (1/sqrt(C)) * log2(e)  -> softmax in log2 domain
    const float SCALEQ = 0.03125f * 1.4426950408889634f;
    dim3 gp(C_ / 128, M_ / 128);    // (8, 64)
    proj_mma<0><<<gp, 256, PROJ_SMEM>>>(x1, Wq, bq, nullptr, qf, SCALEQ);
    proj_mma<0><<<gp, 256, PROJ_SMEM>>>(x2, Wk, bk, nullptr, kf, 1.f);
    proj_mma<0><<<gp, 256, PROJ_SMEM>>>(x2, Wv, bv, nullptr, vf, 1.f);
    attn_mma<<<dim3(T_ / 128, H_, B_), 256, ATT_SMEM>>>(qf, kf, vf, aop);
    proj_mma<1><<<gp, 256, PROJ_SMEM>>>(aop, Wu, bu, out, nullptr, 1.f);
}